// round 1
// baseline (speedup 1.0000x reference)
#include <cuda_runtime.h>

#define VOL (64*256*256)
#define HW  (256*256)

// Scratch (allocation-free: __device__ globals)
__device__ float g_p[VOL];
__device__ float g_q[VOL];
__device__ float g_s[VOL];
__device__ float g_z[VOL];
__device__ float g_res[HW];

// Weights in constant memory -> LDCU/UR operands on the uniform pipe
__constant__ float cW1[4][8][27];
__constant__ float cB1[4][8];
__constant__ float cW2[4][8][27];
__constant__ float cB2[4];
__constant__ float cNT[4][3];   // rows: ntx, nty, ntz, nt

__global__ void clear_pqs_kernel() {
    int i = blockIdx.x * blockDim.x + threadIdx.x;
    g_p[i] = 0.f; g_q[i] = 0.f; g_s[i] = 0.f;
}

// res = (sino - sum_d t) / 64
__global__ void proj_res_kernel(const float* __restrict__ t, const float* __restrict__ sino) {
    int hw = blockIdx.x * blockDim.x + threadIdx.x;
    float s = 0.f;
#pragma unroll 8
    for (int d = 0; d < 64; ++d) s += t[d * HW + hw];
    g_res[hw] = (sino[hw] - s) * (1.0f / 64.0f);
}

// Fused BasicBlock: diff(axis) -> conv1(1->8) -> relu -> conv2(8->1) -> field update.
// B=0: d/dx (W), out=p ; B=1: d/dy (H), out=q ; B=2: d/dz (D), out=s ; B=3: identity, out=g_z
// Tile: 8(H) x 32(W) outputs, sweep over all 64 depths with rolling smem rings.
template <int B>
__global__ __launch_bounds__(352) void block_kernel(const float* __restrict__ t, int casc) {
    __shared__ float zs[4][13][37];        // z ring:   y in [-2..10], x in [-2..34]
    __shared__ float ds[3][12][36];        // diff ring: y in [-2..9],  x in [-2..33]
    __shared__ float hs[3][8][10][34];     // hidden ring: [c][y in -1..8][x in -1..32]
    __shared__ float rs[13][37];           // res/64 tile (same footprint as z slice)

    const int tid = threadIdx.x;
    const int x0 = blockIdx.x * 32;
    const int y0 = blockIdx.y * 8;

    // ---- per-thread precomputed indices ----
    // z / res stage: 481 points, up to 2 tasks
    const int zy_a = tid / 37, zx_a = tid % 37;
    const int tB = tid + 352;
    const bool zb_on = (tB < 481);
    const int zy_b = tB / 37, zx_b = tB % 37;
    const int gza_y = y0 + zy_a - 2, gza_x = x0 + zx_a - 2;
    const int gzb_y = y0 + zy_b - 2, gzb_x = x0 + zx_b - 2;
    const bool zva = (gza_y >= 0 && gza_y < 256 && gza_x >= 0 && gza_x < 256);
    const bool zvb = zb_on && (gzb_y >= 0 && gzb_y < 256 && gzb_x >= 0 && gzb_x < 256);
    const int goff_a = (gza_y << 8) + gza_x;
    const int goff_b = (gzb_y << 8) + gzb_x;
    const int soff_a = zy_a * 37 + zx_a;
    const int soff_b = zy_b * 37 + zx_b;

    // diff stage: 432 points, up to 2 tasks
    const int ddy_a = tid / 36, ddx_a = tid % 36;
    const bool db_on = (tB < 432);
    const int ddy_b = tB / 36, ddx_b = tB % 36;
    const int gda_y = y0 + ddy_a - 2, gda_x = x0 + ddx_a - 2;
    const int gdb_y = y0 + ddy_b - 2, gdb_x = x0 + ddx_b - 2;
    const bool dva = (gda_y >= 0 && gda_y < 256 && gda_x >= 0 && gda_x < 256);
    const bool dvb = db_on && (gdb_y >= 0 && gdb_y < 256 && gdb_x >= 0 && gdb_x < 256);
    const bool dxa_ok = dva && (gda_x < 255);
    const bool dxb_ok = dvb && (gdb_x < 255);
    const bool dya_ok = dva && (gda_y < 255);
    const bool dyb_ok = dvb && (gdb_y < 255);
    const int zoa = ddy_a * 37 + ddx_a;   // diff grid point inside z slice (same origin)
    const int zob = ddy_b * 37 + ddx_b;
    const int doa = ddy_a * 36 + ddx_a;
    const int dob = ddy_b * 36 + ddx_b;

    // hidden stage: 340 points
    const bool h_on = (tid < 340);
    const int hy = tid / 34, hx = tid % 34;
    const int ghy = y0 + hy - 1, ghx = x0 + hx - 1;
    const bool hvol = (ghy >= 0 && ghy < 256 && ghx >= 0 && ghx < 256);

    // output stage: 256 points (warps 0..7)
    const bool o_on = (tid < 256);
    const int oy = tid >> 5, ox = tid & 31;
    const int ooff = ((y0 + oy) << 8) + (x0 + ox);

    const float* oldf;
    float* outf;
    if (B == 0)      { oldf = g_p; outf = g_p; }
    else if (B == 1) { oldf = g_q; outf = g_q; }
    else if (B == 2) { oldf = g_s; outf = g_s; }
    else             { oldf = t;   outf = g_z; }
    const float coef = cNT[B][casc];

    // ---- prologue: res tile + zero the "-1" ring slots ----
    {
        float* rp = &rs[0][0];
        rp[soff_a] = zva ? g_res[goff_a] : 0.f;
        if (zb_on) rp[soff_b] = zvb ? g_res[goff_b] : 0.f;
        float* dz2 = &ds[2][0][0];
        for (int i = tid; i < 12 * 36; i += 352) dz2[i] = 0.f;
        float* hz2 = &hs[2][0][0][0];
        for (int i = tid; i < 8 * 340; i += 352) hz2[i] = 0.f;
    }
    __syncthreads();

    for (int d = -3; d <= 63; ++d) {
        // stage 1: load z slice (d+3) = t + res/64
        const int jz = d + 3;
        if (jz <= 63) {
            const float* tz = t + jz * HW;
            const float* rp = &rs[0][0];
            float* zp = &zs[jz & 3][0][0];
            zp[soff_a] = zva ? (tz[goff_a] + rp[soff_a]) : 0.f;
            if (zb_on) zp[soff_b] = zvb ? (tz[goff_b] + rp[soff_b]) : 0.f;
        }
        __syncthreads();

        // stage 2: diff slice (d+2)
        const int jd = d + 2;
        if (jd >= 0) {
            if (jd <= 63) {
                const float* z0 = &zs[jd & 3][0][0];
                const float* z1 = &zs[(jd + 1) & 3][0][0];
                float* dsl = &ds[jd % 3][0][0];
                float va = 0.f, vb = 0.f;
                if (B == 0) {
                    if (dxa_ok) va = z0[zoa + 1] - z0[zoa];
                    if (dxb_ok) vb = z0[zob + 1] - z0[zob];
                } else if (B == 1) {
                    if (dya_ok) va = z0[zoa + 37] - z0[zoa];
                    if (dyb_ok) vb = z0[zob + 37] - z0[zob];
                } else if (B == 2) {
                    if (dva && jd < 63) va = z1[zoa] - z0[zoa];
                    if (dvb && jd < 63) vb = z1[zob] - z0[zob];
                } else {
                    if (dva) va = z0[zoa];
                    if (dvb) vb = z0[zob];
                }
                dsl[doa] = va;
                if (db_on) dsl[dob] = vb;
            } else if (jd == 64) {
                float* dsl = &ds[64 % 3][0][0];
                for (int i = tid; i < 12 * 36; i += 352) dsl[i] = 0.f;
            }
        }
        __syncthreads();

        // stage 3: hidden slice (d+1): conv1 + relu
        const int jh = d + 1;
        if (jh >= 0) {
            if (jh <= 63) {
                if (h_on) {
                    float h[8];
#pragma unroll
                    for (int c = 0; c < 8; ++c) h[c] = cB1[B][c];
                    const float* dpl0 = &ds[(jh + 2) % 3][0][0] + hy * 36 + hx;
                    const float* dpl1 = &ds[jh % 3][0][0]       + hy * 36 + hx;
                    const float* dpl2 = &ds[(jh + 1) % 3][0][0] + hy * 36 + hx;
#pragma unroll
                    for (int kz = 0; kz < 3; ++kz) {
                        const float* dp = (kz == 0) ? dpl0 : (kz == 1) ? dpl1 : dpl2;
#pragma unroll
                        for (int ky = 0; ky < 3; ++ky) {
#pragma unroll
                            for (int kx = 0; kx < 3; ++kx) {
                                const float dv = dp[ky * 36 + kx];
                                const int tap = (kz * 3 + ky) * 3 + kx;
#pragma unroll
                                for (int c = 0; c < 8; ++c)
                                    h[c] = fmaf(cW1[B][c][tap], dv, h[c]);
                            }
                        }
                    }
                    float* hp = &hs[jh % 3][0][0][0] + hy * 34 + hx;
#pragma unroll
                    for (int c = 0; c < 8; ++c)
                        hp[c * 340] = hvol ? fmaxf(h[c], 0.f) : 0.f;
                }
            } else {
                float* hz = &hs[jh % 3][0][0][0];
                for (int i = tid; i < 8 * 340; i += 352) hz[i] = 0.f;
            }
        }
        __syncthreads();

        // stage 4: conv2 + field update at depth d
        if (d >= 0 && o_on) {
            float a0 = cB2[B], a1 = 0.f, a2 = 0.f, a3 = 0.f;
            const float* hp0 = &hs[(d + 2) % 3][0][0][0] + oy * 34 + ox;
            const float* hp1 = &hs[d % 3][0][0][0]       + oy * 34 + ox;
            const float* hp2 = &hs[(d + 1) % 3][0][0][0] + oy * 34 + ox;
#pragma unroll
            for (int kz = 0; kz < 3; ++kz) {
                const float* hp = (kz == 0) ? hp0 : (kz == 1) ? hp1 : hp2;
#pragma unroll
                for (int c = 0; c < 8; ++c) {
#pragma unroll
                    for (int ky = 0; ky < 3; ++ky) {
#pragma unroll
                        for (int kx = 0; kx < 3; ++kx) {
                            const float hv = hp[c * 340 + ky * 34 + kx];
                            const float w = cW2[B][c][(kz * 3 + ky) * 3 + kx];
                            const int lane = (c & 3);
                            if (lane == 0)      a0 = fmaf(w, hv, a0);
                            else if (lane == 1) a1 = fmaf(w, hv, a1);
                            else if (lane == 2) a2 = fmaf(w, hv, a2);
                            else                a3 = fmaf(w, hv, a3);
                        }
                    }
                }
            }
            const float acc = (a0 + a1) + (a2 + a3);
            const int gidx = (d << 16) + ooff;
            const float old = oldf[gidx];
            outf[gidx] = fmaf(coef, old - acc, old);
        }
    }
}

// t_new = fdiff_t(p,x) + fdiff_t(q,y) + fdiff_t(s,z) + z_
__global__ void combine_kernel(float* __restrict__ tout) {
    int i = blockIdx.x * blockDim.x + threadIdx.x;
    int d = i >> 16;
    int hw = i & 65535;
    int y = hw >> 8;
    int x = hw & 255;
    float v = g_z[i];
    v += (x > 0   ? g_p[i - 1]   : 0.f) - (x < 255 ? g_p[i] : 0.f);
    v += (y > 0   ? g_q[i - 256] : 0.f) - (y < 255 ? g_q[i] : 0.f);
    v += (d > 0   ? g_s[i - HW]  : 0.f) - (d < 63  ? g_s[i] : 0.f);
    tout[i] = v;
}

extern "C" void kernel_launch(void* const* d_in, const int* in_sizes, int n_in,
                              void* d_out, int out_size) {
    const float* image = (const float*)d_in[0];
    const float* sino  = (const float*)d_in[1];
    float* out = (float*)d_out;

    // weights -> constant memory (D2D memcpy-to-symbol: graph-capturable)
    cudaMemcpyToSymbolAsync(cW1, d_in[2], 864 * sizeof(float), 0, cudaMemcpyDeviceToDevice, 0);
    cudaMemcpyToSymbolAsync(cB1, d_in[3], 32  * sizeof(float), 0, cudaMemcpyDeviceToDevice, 0);
    cudaMemcpyToSymbolAsync(cW2, d_in[4], 864 * sizeof(float), 0, cudaMemcpyDeviceToDevice, 0);
    cudaMemcpyToSymbolAsync(cB2, d_in[5], 4   * sizeof(float), 0, cudaMemcpyDeviceToDevice, 0);
    for (int k = 0; k < 4; ++k)
        cudaMemcpyToSymbolAsync(cNT, d_in[6 + k], 3 * sizeof(float),
                                k * 3 * sizeof(float), cudaMemcpyDeviceToDevice, 0);

    // outs[0] = image; t for cascade c lives in out + c*VOL
    cudaMemcpyAsync(out, image, (size_t)VOL * sizeof(float), cudaMemcpyDeviceToDevice, 0);
    clear_pqs_kernel<<<VOL / 256, 256>>>();

    dim3 bgrid(8, 32);   // W/32 x H/8
    for (int c = 0; c < 3; ++c) {
        const float* t = out + (size_t)c * VOL;
        proj_res_kernel<<<HW / 256, 256>>>(t, sino);
        block_kernel<0><<<bgrid, 352>>>(t, c);
        block_kernel<1><<<bgrid, 352>>>(t, c);
        block_kernel<2><<<bgrid, 352>>>(t, c);
        block_kernel<3><<<bgrid, 352>>>(t, c);
        combine_kernel<<<VOL / 256, 256>>>(out + (size_t)(c + 1) * VOL);
    }
}

// round 3
// speedup vs baseline: 1.4140x; 1.4140x over previous
#include <cuda_runtime.h>

#define VOL (64*256*256)
#define HW  (256*256)

// Scratch (allocation-free: __device__ globals)
__device__ float g_p[VOL];
__device__ float g_q[VOL];
__device__ float g_s[VOL];
__device__ float g_z[VOL];
__device__ float g_res[HW];

// Weights in constant memory
__constant__ float cW1[4][8][27];
__constant__ float cB1[4][8];
__constant__ float cW2[4][8][27];
__constant__ float cB2[4];
__constant__ float cNT[4][3];   // rows: ntx, nty, ntz, nt

__global__ void clear_pqs_kernel() {
    int i = blockIdx.x * blockDim.x + threadIdx.x;
    g_p[i] = 0.f; g_q[i] = 0.f; g_s[i] = 0.f;
}

// res = (sino - sum_d t) / 64
__global__ void proj_res_kernel(const float* __restrict__ t, const float* __restrict__ sino) {
    int hw = blockIdx.x * blockDim.x + threadIdx.x;
    float s = 0.f;
#pragma unroll 8
    for (int d = 0; d < 64; ++d) s += t[d * HW + hw];
    g_res[hw] = (sino[hw] - s) * (1.0f / 64.0f);
}

struct Smem {
    float zs[4][13][37];        // z ring:     y in [-2..10], x in [-2..34]
    float ds[3][12][36];        // diff ring:  y in [-2..9],  x in [-2..33]
    float hs[3][8][10][34];     // hidden ring:[c][y in -1..8][x in -1..32]
    float rs[13][37];           // res/64 tile
};

// Fused BasicBlock body: diff(axis) -> conv1(1->8) -> relu -> conv2(8->1) -> field update.
// B=0: d/dx (W), out=p ; B=1: d/dy (H), out=q ; B=2: d/dz (D), out=s ; B=3: identity, out=g_z
template <int B>
__device__ __forceinline__ void block_body(Smem& sm, const float* __restrict__ t, int casc) {
    const int tid = threadIdx.x;
    const int x0 = blockIdx.x * 32;
    const int y0 = blockIdx.y * 8;

    // z / res stage: 481 points, up to 2 tasks per thread
    const int zy_a = tid / 37, zx_a = tid % 37;
    const int tB = tid + 352;
    const bool zb_on = (tB < 481);
    const int zy_b = tB / 37, zx_b = tB % 37;
    const int gza_y = y0 + zy_a - 2, gza_x = x0 + zx_a - 2;
    const int gzb_y = y0 + zy_b - 2, gzb_x = x0 + zx_b - 2;
    const bool zva = (gza_y >= 0 && gza_y < 256 && gza_x >= 0 && gza_x < 256);
    const bool zvb = zb_on && (gzb_y >= 0 && gzb_y < 256 && gzb_x >= 0 && gzb_x < 256);
    const int goff_a = (gza_y << 8) + gza_x;
    const int goff_b = (gzb_y << 8) + gzb_x;
    const int soff_a = zy_a * 37 + zx_a;
    const int soff_b = zy_b * 37 + zx_b;

    // diff stage: 432 points
    const int ddy_a = tid / 36, ddx_a = tid % 36;
    const bool db_on = (tB < 432);
    const int ddy_b = tB / 36, ddx_b = tB % 36;
    const int gda_y = y0 + ddy_a - 2, gda_x = x0 + ddx_a - 2;
    const int gdb_y = y0 + ddy_b - 2, gdb_x = x0 + ddx_b - 2;
    const bool dva = (gda_y >= 0 && gda_y < 256 && gda_x >= 0 && gda_x < 256);
    const bool dvb = db_on && (gdb_y >= 0 && gdb_y < 256 && gdb_x >= 0 && gdb_x < 256);
    const bool dxa_ok = dva && (gda_x < 255);
    const bool dxb_ok = dvb && (gdb_x < 255);
    const bool dya_ok = dva && (gda_y < 255);
    const bool dyb_ok = dvb && (gdb_y < 255);
    const int zoa = ddy_a * 37 + ddx_a;
    const int zob = ddy_b * 37 + ddx_b;
    const int doa = ddy_a * 36 + ddx_a;
    const int dob = ddy_b * 36 + ddx_b;

    // hidden stage: 340 points
    const bool h_on = (tid < 340);
    const int hy = tid / 34, hx = tid % 34;
    const int ghy = y0 + hy - 1, ghx = x0 + hx - 1;
    const bool hvol = (ghy >= 0 && ghy < 256 && ghx >= 0 && ghx < 256);

    // output stage: 128 threads, each computes 2 y-rows x 1 x
    const bool o_on = (tid < 128);
    const int oy2 = (tid >> 5) & 3;       // 0..3
    const int ox  = tid & 31;
    const int y0l = oy2 * 2;              // local row 0,2,4,6
    const int obase = y0l * 34 + ox;
    const int ooff = ((y0 + y0l) << 8) + (x0 + ox);

    const float* oldf;
    float* outf;
    if (B == 0)      { oldf = g_p; outf = g_p; }
    else if (B == 1) { oldf = g_q; outf = g_q; }
    else if (B == 2) { oldf = g_s; outf = g_s; }
    else             { oldf = t;   outf = g_z; }
    const float coef = cNT[B][casc];

    // prologue: res tile + zero the "-1" ring slots
    {
        float* rp = &sm.rs[0][0];
        rp[soff_a] = zva ? g_res[goff_a] : 0.f;
        if (zb_on) rp[soff_b] = zvb ? g_res[goff_b] : 0.f;
        float* dz2 = &sm.ds[2][0][0];
        for (int i = tid; i < 12 * 36; i += 352) dz2[i] = 0.f;
        float* hz2 = &sm.hs[2][0][0][0];
        for (int i = tid; i < 8 * 340; i += 352) hz2[i] = 0.f;
    }
    __syncthreads();

    for (int d = -3; d <= 63; ++d) {
        // stage 1: load z slice (d+3) = t + res/64
        const int jz = d + 3;
        if (jz <= 63) {
            const float* tz = t + jz * HW;
            const float* rp = &sm.rs[0][0];
            float* zp = &sm.zs[jz & 3][0][0];
            zp[soff_a] = zva ? (tz[goff_a] + rp[soff_a]) : 0.f;
            if (zb_on) zp[soff_b] = zvb ? (tz[goff_b] + rp[soff_b]) : 0.f;
        }
        __syncthreads();

        // stage 2: diff slice (d+2)
        const int jd = d + 2;
        if (jd >= 0) {
            if (jd <= 63) {
                const float* z0 = &sm.zs[jd & 3][0][0];
                const float* z1 = &sm.zs[(jd + 1) & 3][0][0];
                float* dsl = &sm.ds[jd % 3][0][0];
                float va = 0.f, vb = 0.f;
                if (B == 0) {
                    if (dxa_ok) va = z0[zoa + 1] - z0[zoa];
                    if (dxb_ok) vb = z0[zob + 1] - z0[zob];
                } else if (B == 1) {
                    if (dya_ok) va = z0[zoa + 37] - z0[zoa];
                    if (dyb_ok) vb = z0[zob + 37] - z0[zob];
                } else if (B == 2) {
                    if (dva && jd < 63) va = z1[zoa] - z0[zoa];
                    if (dvb && jd < 63) vb = z1[zob] - z0[zob];
                } else {
                    if (dva) va = z0[zoa];
                    if (dvb) vb = z0[zob];
                }
                dsl[doa] = va;
                if (db_on) dsl[dob] = vb;
            } else if (jd == 64) {
                float* dsl = &sm.ds[64 % 3][0][0];
                for (int i = tid; i < 12 * 36; i += 352) dsl[i] = 0.f;
            }
        }
        __syncthreads();

        // stage 3: hidden slice (d+1): conv1 + relu
        const int jh = d + 1;
        if (jh >= 0) {
            if (jh <= 63) {
                if (h_on) {
                    float h[8];
#pragma unroll
                    for (int c = 0; c < 8; ++c) h[c] = cB1[B][c];
                    const float* dpl0 = &sm.ds[(jh + 2) % 3][0][0] + hy * 36 + hx;
                    const float* dpl1 = &sm.ds[jh % 3][0][0]       + hy * 36 + hx;
                    const float* dpl2 = &sm.ds[(jh + 1) % 3][0][0] + hy * 36 + hx;
#pragma unroll
                    for (int kz = 0; kz < 3; ++kz) {
                        const float* dp = (kz == 0) ? dpl0 : (kz == 1) ? dpl1 : dpl2;
#pragma unroll
                        for (int ky = 0; ky < 3; ++ky) {
#pragma unroll
                            for (int kx = 0; kx < 3; ++kx) {
                                const float dv = dp[ky * 36 + kx];
                                const int tap = (kz * 3 + ky) * 3 + kx;
#pragma unroll
                                for (int c = 0; c < 8; ++c)
                                    h[c] = fmaf(cW1[B][c][tap], dv, h[c]);
                            }
                        }
                    }
                    float* hp = &sm.hs[jh % 3][0][0][0] + hy * 34 + hx;
#pragma unroll
                    for (int c = 0; c < 8; ++c)
                        hp[c * 340] = hvol ? fmaxf(h[c], 0.f) : 0.f;
                }
            } else {
                float* hz = &sm.hs[jh % 3][0][0][0];
                for (int i = tid; i < 8 * 340; i += 352) hz[i] = 0.f;
            }
        }
        __syncthreads();

        // stage 4: conv2 + field update at depth d — 2 y-rows per thread
        if (d >= 0 && o_on) {
            float a00 = cB2[B], a01 = 0.f;   // output row y0l
            float a10 = cB2[B], a11 = 0.f;   // output row y0l+1
            const float* hp0 = &sm.hs[(d + 2) % 3][0][0][0] + obase;
            const float* hp1 = &sm.hs[d % 3][0][0][0]       + obase;
            const float* hp2 = &sm.hs[(d + 1) % 3][0][0][0] + obase;
#pragma unroll
            for (int kz = 0; kz < 3; ++kz) {
                const float* hp = (kz == 0) ? hp0 : (kz == 1) ? hp1 : hp2;
#pragma unroll
                for (int c = 0; c < 8; ++c) {
#pragma unroll
                    for (int r = 0; r < 4; ++r) {
#pragma unroll
                        for (int kx = 0; kx < 3; ++kx) {
                            const float v = hp[c * 340 + r * 34 + kx];
                            if (r < 3) {
                                const float w0 = cW2[B][c][kz * 9 + r * 3 + kx];
                                if (c & 1) a01 = fmaf(w0, v, a01);
                                else       a00 = fmaf(w0, v, a00);
                            }
                            if (r > 0) {
                                const float w1 = cW2[B][c][kz * 9 + (r - 1) * 3 + kx];
                                if (c & 1) a11 = fmaf(w1, v, a11);
                                else       a10 = fmaf(w1, v, a10);
                            }
                        }
                    }
                }
            }
            const float acc0 = a00 + a01;
            const float acc1 = a10 + a11;
            const int gidx = (d << 16) + ooff;
            const float old0 = oldf[gidx];
            const float old1 = oldf[gidx + 256];
            outf[gidx]       = fmaf(coef, old0 - acc0, old0);
            outf[gidx + 256] = fmaf(coef, old1 - acc1, old1);
        }
        __syncthreads();
    }
}

__global__ __launch_bounds__(352) void fused_blocks_kernel(const float* __restrict__ t, int casc) {
    __shared__ Smem sm;
    switch (blockIdx.z) {
        case 0: block_body<0>(sm, t, casc); break;
        case 1: block_body<1>(sm, t, casc); break;
        case 2: block_body<2>(sm, t, casc); break;
        default: block_body<3>(sm, t, casc); break;
    }
}

// t_new = fdiff_t(p,x) + fdiff_t(q,y) + fdiff_t(s,z) + z_
__global__ void combine_kernel(float* __restrict__ tout) {
    int i = blockIdx.x * blockDim.x + threadIdx.x;
    int d = i >> 16;
    int hw = i & 65535;
    int y = hw >> 8;
    int x = hw & 255;
    float v = g_z[i];
    v += (x > 0   ? g_p[i - 1]   : 0.f) - (x < 255 ? g_p[i] : 0.f);
    v += (y > 0   ? g_q[i - 256] : 0.f) - (y < 255 ? g_q[i] : 0.f);
    v += (d > 0   ? g_s[i - HW]  : 0.f) - (d < 63  ? g_s[i] : 0.f);
    tout[i] = v;
}

extern "C" void kernel_launch(void* const* d_in, const int* in_sizes, int n_in,
                              void* d_out, int out_size) {
    const float* image = (const float*)d_in[0];
    const float* sino  = (const float*)d_in[1];
    float* out = (float*)d_out;

    cudaMemcpyToSymbolAsync(cW1, d_in[2], 864 * sizeof(float), 0, cudaMemcpyDeviceToDevice, 0);
    cudaMemcpyToSymbolAsync(cB1, d_in[3], 32  * sizeof(float), 0, cudaMemcpyDeviceToDevice, 0);
    cudaMemcpyToSymbolAsync(cW2, d_in[4], 864 * sizeof(float), 0, cudaMemcpyDeviceToDevice, 0);
    cudaMemcpyToSymbolAsync(cB2, d_in[5], 4   * sizeof(float), 0, cudaMemcpyDeviceToDevice, 0);
    for (int k = 0; k < 4; ++k)
        cudaMemcpyToSymbolAsync(cNT, d_in[6 + k], 3 * sizeof(float),
                                k * 3 * sizeof(float), cudaMemcpyDeviceToDevice, 0);

    cudaMemcpyAsync(out, image, (size_t)VOL * sizeof(float), cudaMemcpyDeviceToDevice, 0);
    clear_pqs_kernel<<<VOL / 256, 256>>>();

    dim3 bgrid(8, 32, 4);   // W/32 x H/8 x 4 BasicBlocks
    for (int c = 0; c < 3; ++c) {
        const float* t = out + (size_t)c * VOL;
        proj_res_kernel<<<HW / 256, 256>>>(t, sino);
        fused_blocks_kernel<<<bgrid, 352>>>(t, c);
        combine_kernel<<<VOL / 256, 256>>>(out + (size_t)(c + 1) * VOL);
    }
}

// round 4
// speedup vs baseline: 1.6481x; 1.1655x over previous
#include <cuda_runtime.h>

typedef unsigned long long ull;

#define VOL (64*256*256)
#define HW  (256*256)

// Scratch (allocation-free: __device__ globals)
__device__ float g_p[VOL];
__device__ float g_q[VOL];
__device__ float g_s[VOL];
__device__ float g_z[VOL];
__device__ float g_res[HW];
__device__ float2 g_pk1[432];
__device__ float2 g_pk2[432];

// Weights in constant memory
__constant__ float cW1[4][8][27];
__constant__ float cB1[4][8];
__constant__ float cW2[4][8][27];
__constant__ float cB2[4];
__constant__ float cNT[4][3];          // rows: ntx, nty, ntz, nt
__constant__ float2 cW1p[4][27][4];    // [B][tap][cpair] packed (c=2cp, 2cp+1)
__constant__ float2 cW2p[4][27][4];

__device__ __forceinline__ void ffma2(ull& d, ull a, ull b) {
    asm("fma.rn.f32x2 %0, %1, %2, %0;" : "+l"(d) : "l"(a), "l"(b));
}
__device__ __forceinline__ ull pack2(float x, float y) {
    ull r; asm("mov.b64 %0, {%1, %2};" : "=l"(r) : "f"(x), "f"(y)); return r;
}
__device__ __forceinline__ float2 u2f(ull v) {
    float2 r; asm("mov.b64 {%0, %1}, %2;" : "=f"(r.x), "=f"(r.y) : "l"(v)); return r;
}

// Repack weight channel-pairs into float2 tables (device-side; copied to constant after)
__global__ void repack_kernel() {
    int i = threadIdx.x;
    if (i < 432) {
        int B = i / 108, r = i % 108, tap = r / 4, cp = r % 4;
        g_pk1[i] = make_float2(cW1[B][2*cp][tap], cW1[B][2*cp+1][tap]);
        g_pk2[i] = make_float2(cW2[B][2*cp][tap], cW2[B][2*cp+1][tap]);
    }
}

__global__ void clear_pqs_kernel() {
    int i = blockIdx.x * blockDim.x + threadIdx.x;
    g_p[i] = 0.f; g_q[i] = 0.f; g_s[i] = 0.f;
}

// res = (sino - sum_d t) / 64   (used only for cascade 0)
__global__ void proj_res_kernel(const float* __restrict__ t, const float* __restrict__ sino) {
    int hw = blockIdx.x * blockDim.x + threadIdx.x;
    float s = 0.f;
#pragma unroll 8
    for (int d = 0; d < 64; ++d) s += t[d * HW + hw];
    g_res[hw] = (sino[hw] - s) * (1.0f / 64.0f);
}

// t_new = fdiff_t(p,x)+fdiff_t(q,y)+fdiff_t(s,z)+z_ ; also g_res for next cascade
__global__ void combine_proj_kernel(float* __restrict__ tout, const float* __restrict__ sino) {
    const int hw = blockIdx.x * blockDim.x + threadIdx.x;
    const int y = hw >> 8, x = hw & 255;
    float sum = 0.f, s_prev = 0.f;
    int i = hw;
#pragma unroll 4
    for (int d = 0; d < 64; ++d, i += HW) {
        const float s_cur = g_s[i];
        float v = g_z[i];
        v += (x > 0   ? g_p[i - 1]   : 0.f) - (x < 255 ? g_p[i] : 0.f);
        v += (y > 0   ? g_q[i - 256] : 0.f) - (y < 255 ? g_q[i] : 0.f);
        v += s_prev - (d < 63 ? s_cur : 0.f);
        tout[i] = v;
        sum += v;
        s_prev = s_cur;
    }
    g_res[hw] = (sino[hw] - sum) * (1.0f / 64.0f);
}

struct Smem {
    float2 hs2[3][4][10][34];  // hidden ring: [slice][cpair][y(-1..8)][x(-1..32)]
    float  zs[4][481];         // z ring: 13x37 (y -2..10, x -2..34)
    float  ds[3][432];         // diff ring: 12x36 (y -2..9, x -2..33)
    float  rs[481];            // res/64 tile
};

// Skewed pipeline, 2 barriers/iter. Iteration i: [A] z[i], diff[i-2], out[i-5] | [B] hidden[i-3]
template <int B>
__device__ __forceinline__ void block_body(Smem& sm, const float* __restrict__ t, int casc) {
    const int tid = threadIdx.x;
    const int x0 = blockIdx.x * 32;
    const int y0 = blockIdx.y * 8;

    // ---- conv2 role (tid < 64): 2y x 2x outputs ----
    const int y0l = ((tid >> 4) & 3) * 2;     // 0,2,4,6
    const int x0l = (tid & 15) * 2;           // 0..30
    const int ooff = ((y0 + y0l) << 8) + (x0 + x0l);
    const int hbase = y0l * 34 + x0l;         // float2 elements

    // ---- loader role (tid >= 64): l = tid-64 in [0,288) ----
    const int l = tid - 64;
    // z task A (idx=l) and B (idx=l+288 if l<193)
    const int zyA = l / 37, zxA = l % 37;
    const int gyA = y0 + zyA - 2, gxA = x0 + zxA - 2;
    const bool zvA = (gyA >= 0 && gyA < 256 && gxA >= 0 && gxA < 256);
    const int goA = (gyA << 8) + gxA;
    const int lB = l + 288;
    const int zyB = lB / 37, zxB = lB % 37;
    const int gyB = y0 + zyB - 2, gxB = x0 + zxB - 2;
    const bool zvB = (l < 193) && (gyB >= 0 && gyB < 256 && gxB >= 0 && gxB < 256);
    const int goB = (gyB << 8) + gxB;
    // diff task A (idx=l) and B (idx=l+288 if l<144)
    const int dyA = l / 36, dxA = l % 36;
    const int gdyA = y0 + dyA - 2, gdxA = x0 + dxA - 2;
    const bool dvA = (gdyA >= 0 && gdyA < 256 && gdxA >= 0 && gdxA < 256);
    const bool okA = dvA && ((B == 0) ? (gdxA < 255) : (B == 1) ? (gdyA < 255) : true);
    const int zoA = dyA * 37 + dxA;
    const int dyB2 = lB / 36, dxB2 = lB % 36;
    const int gdyB = y0 + dyB2 - 2, gdxB = x0 + dxB2 - 2;
    const bool dvB = (l < 144) && (gdyB >= 0 && gdyB < 256 && gdxB >= 0 && gdxB < 256);
    const bool okB = dvB && ((B == 0) ? (gdxB < 255) : (B == 1) ? (gdyB < 255) : true);
    const int zoB = dyB2 * 37 + dxB2;

    // ---- hidden role (tid < 340) ----
    const int hy = tid / 34, hx = tid % 34;
    const int ghy = y0 + hy - 1, ghx = x0 + hx - 1;
    const bool hvol = (ghy >= 0 && ghy < 256 && ghx >= 0 && ghx < 256);
    const int dbase = hy * 36 + hx;

    const float* oldf;
    float* outf;
    if (B == 0)      { oldf = g_p; outf = g_p; }
    else if (B == 1) { oldf = g_q; outf = g_q; }
    else if (B == 2) { oldf = g_s; outf = g_s; }
    else             { oldf = t;   outf = g_z; }
    const float coef = cNT[B][casc];

    float2* const hflat = &sm.hs2[0][0][0][0];
    const ull* const W1 = reinterpret_cast<const ull*>(cW1p[B]);
    const ull* const W2 = reinterpret_cast<const ull*>(cW2p[B]);

    // prologue: res tile + zero slot-2 rings (diff[-1], hidden[-1])
    for (int idx = tid; idx < 481; idx += 352) {
        const int zy = idx / 37, zx = idx % 37;
        const int gy = y0 + zy - 2, gx = x0 + zx - 2;
        const bool v = (gy >= 0 && gy < 256 && gx >= 0 && gx < 256);
        sm.rs[idx] = v ? g_res[(gy << 8) + gx] : 0.f;
    }
    for (int idx = tid; idx < 432; idx += 352) sm.ds[2][idx] = 0.f;
    {
        float* hz = reinterpret_cast<float*>(&sm.hs2[2][0][0][0]);
        for (int idx = tid; idx < 2720; idx += 352) hz[idx] = 0.f;
    }
    __syncthreads();

#pragma unroll 1
    for (int i = 0; i <= 68; ++i) {
        const int m0 = i % 3;
        const int m1 = (m0 == 2) ? 0 : m0 + 1;
        const int m2 = (m1 == 2) ? 0 : m1 + 1;

        // ================= phase A =================
        if (tid < 64) {
            if (i >= 5) {
                const int o = i - 5;
                const int gidx = (o << 16) + ooff;
                const float2 old0 = *reinterpret_cast<const float2*>(&oldf[gidx]);
                const float2 old1 = *reinterpret_cast<const float2*>(&oldf[gidx + 256]);
                ull a00 = 0, a01 = 0, a10 = 0, a11 = 0;
#pragma unroll
                for (int kz = 0; kz < 3; ++kz) {
                    const int sl = (kz == 0) ? m0 : (kz == 1) ? m1 : m2;
                    const float2* hb = hflat + sl * 1360 + hbase;
#pragma unroll
                    for (int cp = 0; cp < 4; ++cp) {
                        const float2* hc = hb + cp * 340;
                        const int tb = kz * 36 + cp;
#pragma unroll
                        for (int r = 0; r < 4; ++r) {
                            const ulonglong2 va = *reinterpret_cast<const ulonglong2*>(hc + r * 34);
                            const ulonglong2 vb = *reinterpret_cast<const ulonglong2*>(hc + r * 34 + 2);
                            if (r < 3) {
                                const int w = tb + r * 12;
                                ffma2(a00, W2[w],     va.x);
                                ffma2(a00, W2[w + 4], va.y);
                                ffma2(a00, W2[w + 8], vb.x);
                                ffma2(a01, W2[w],     va.y);
                                ffma2(a01, W2[w + 4], vb.x);
                                ffma2(a01, W2[w + 8], vb.y);
                            }
                            if (r > 0) {
                                const int w = tb + (r - 1) * 12;
                                ffma2(a10, W2[w],     va.x);
                                ffma2(a10, W2[w + 4], va.y);
                                ffma2(a10, W2[w + 8], vb.x);
                                ffma2(a11, W2[w],     va.y);
                                ffma2(a11, W2[w + 4], vb.x);
                                ffma2(a11, W2[w + 8], vb.y);
                            }
                        }
                    }
                }
                const float bz = cB2[B];
                const float2 e00 = u2f(a00), e01 = u2f(a01), e10 = u2f(a10), e11 = u2f(a11);
                const float s00 = bz + e00.x + e00.y;
                const float s01 = bz + e01.x + e01.y;
                const float s10 = bz + e10.x + e10.y;
                const float s11 = bz + e11.x + e11.y;
                float2 o0, o1;
                o0.x = fmaf(coef, old0.x - s00, old0.x);
                o0.y = fmaf(coef, old0.y - s01, old0.y);
                o1.x = fmaf(coef, old1.x - s10, old1.x);
                o1.y = fmaf(coef, old1.y - s11, old1.y);
                *reinterpret_cast<float2*>(&outf[gidx])       = o0;
                *reinterpret_cast<float2*>(&outf[gidx + 256]) = o1;
            }
        } else {
            // z slice i
            if (i <= 63) {
                const float* tz = t + i * HW;
                float* zp = sm.zs[i & 3];
                zp[l] = zvA ? (tz[goA] + sm.rs[l]) : 0.f;
                if (l < 193) zp[lB] = zvB ? (tz[goB] + sm.rs[lB]) : 0.f;
            }
            // diff slice e = i-2
            const int e = i - 2;
            if (e >= 0 && e <= 63) {
                const float* z0 = sm.zs[e & 3];
                const float* z1 = sm.zs[(e + 1) & 3];
                float* dd = sm.ds[m1];
                float va = 0.f, vb = 0.f;
                if (B == 0) {
                    if (okA) va = z0[zoA + 1] - z0[zoA];
                    if (okB) vb = z0[zoB + 1] - z0[zoB];
                } else if (B == 1) {
                    if (okA) va = z0[zoA + 37] - z0[zoA];
                    if (okB) vb = z0[zoB + 37] - z0[zoB];
                } else if (B == 2) {
                    if (okA && e < 63) va = z1[zoA] - z0[zoA];
                    if (okB && e < 63) vb = z1[zoB] - z0[zoB];
                } else {
                    if (okA) va = z0[zoA];
                    if (okB) vb = z0[zoB];
                }
                dd[l] = va;
                if (l < 144) dd[lB] = vb;
            } else if (e == 64) {
                float* dd = sm.ds[m1];
                dd[l] = 0.f;
                if (l < 144) dd[lB] = 0.f;
            }
        }
        __syncthreads();

        // ================= phase B: hidden h = i-3 =================
        const int h = i - 3;
        if (h >= 0 && h <= 63) {
            if (tid < 340) {
                ull h2[4];
#pragma unroll
                for (int cp = 0; cp < 4; ++cp)
                    h2[cp] = *reinterpret_cast<const ull*>(&cB1[B][2 * cp]);
#pragma unroll
                for (int kz = 0; kz < 3; ++kz) {
                    const int sl = (kz == 0) ? m2 : (kz == 1) ? m0 : m1;
                    const float* dp = sm.ds[sl] + dbase;
#pragma unroll
                    for (int ky = 0; ky < 3; ++ky) {
#pragma unroll
                        for (int kx = 0; kx < 3; ++kx) {
                            const float dv = dp[ky * 36 + kx];
                            const ull dd = pack2(dv, dv);
                            const int tap = (kz * 3 + ky) * 3 + kx;
                            ffma2(h2[0], W1[tap * 4 + 0], dd);
                            ffma2(h2[1], W1[tap * 4 + 1], dd);
                            ffma2(h2[2], W1[tap * 4 + 2], dd);
                            ffma2(h2[3], W1[tap * 4 + 3], dd);
                        }
                    }
                }
                float2* hw = hflat + m0 * 1360 + hy * 34 + hx;
#pragma unroll
                for (int cp = 0; cp < 4; ++cp) {
                    float2 v = u2f(h2[cp]);
                    if (hvol) { v.x = fmaxf(v.x, 0.f); v.y = fmaxf(v.y, 0.f); }
                    else      { v.x = 0.f; v.y = 0.f; }
                    hw[cp * 340] = v;
                }
            }
        } else if (h == 64) {
            float* hz = reinterpret_cast<float*>(hflat + m0 * 1360);
            for (int idx = tid; idx < 2720; idx += 352) hz[idx] = 0.f;
        }
        __syncthreads();
    }
}

__global__ __launch_bounds__(352, 4) void fused_blocks_kernel(const float* __restrict__ t, int casc) {
    __shared__ Smem sm;
    switch (blockIdx.z) {
        case 0: block_body<0>(sm, t, casc); break;
        case 1: block_body<1>(sm, t, casc); break;
        case 2: block_body<2>(sm, t, casc); break;
        default: block_body<3>(sm, t, casc); break;
    }
}

extern "C" void kernel_launch(void* const* d_in, const int* in_sizes, int n_in,
                              void* d_out, int out_size) {
    const float* image = (const float*)d_in[0];
    const float* sino  = (const float*)d_in[1];
    float* out = (float*)d_out;

    cudaMemcpyToSymbolAsync(cW1, d_in[2], 864 * sizeof(float), 0, cudaMemcpyDeviceToDevice, 0);
    cudaMemcpyToSymbolAsync(cB1, d_in[3], 32  * sizeof(float), 0, cudaMemcpyDeviceToDevice, 0);
    cudaMemcpyToSymbolAsync(cW2, d_in[4], 864 * sizeof(float), 0, cudaMemcpyDeviceToDevice, 0);
    cudaMemcpyToSymbolAsync(cB2, d_in[5], 4   * sizeof(float), 0, cudaMemcpyDeviceToDevice, 0);
    for (int k = 0; k < 4; ++k)
        cudaMemcpyToSymbolAsync(cNT, d_in[6 + k], 3 * sizeof(float),
                                k * 3 * sizeof(float), cudaMemcpyDeviceToDevice, 0);

    // repack weight pairs on device, then promote to constant
    repack_kernel<<<1, 432>>>();
    void *p1 = nullptr, *p2 = nullptr;
    cudaGetSymbolAddress(&p1, g_pk1);
    cudaGetSymbolAddress(&p2, g_pk2);
    cudaMemcpyToSymbolAsync(cW1p, p1, 432 * sizeof(float2), 0, cudaMemcpyDeviceToDevice, 0);
    cudaMemcpyToSymbolAsync(cW2p, p2, 432 * sizeof(float2), 0, cudaMemcpyDeviceToDevice, 0);

    cudaMemcpyAsync(out, image, (size_t)VOL * sizeof(float), cudaMemcpyDeviceToDevice, 0);
    clear_pqs_kernel<<<VOL / 256, 256>>>();
    proj_res_kernel<<<HW / 256, 256>>>(out, sino);

    dim3 bgrid(8, 32, 4);   // W/32 x H/8 x 4 BasicBlocks
    for (int c = 0; c < 3; ++c) {
        const float* t = out + (size_t)c * VOL;
        fused_blocks_kernel<<<bgrid, 352>>>(t, c);
        combine_proj_kernel<<<HW / 256, 256>>>(out + (size_t)(c + 1) * VOL, sino);
    }
}